// round 14
// baseline (speedup 1.0000x reference)
#include <cuda_runtime.h>
#include <cstdint>

// PointNet++ SA layer, fused producer/consumer, 1024-thread blocks:
//   blocks 0-7: FPS (512 active thr x 8 pts, packed f32x2) streaming centers
//   all blocks: persistent consumers (ball query + tf32 mma.sync MLP + max agg)
#define NB    8
#define NPER  4096
#define NS    1024
#define KNBR  64
#define CIN   64
#define HDIM  128
#define NCTR  (NB*NPER/4)  // 8192
#define NTILES (NCTR/2)    // 4096 tiles of 128 rows (2 centers x 64 slots)
#define CAP   1024
#define R2    0.04f

// SMEM strides (floats). Chosen for conflict-free mma fragment LDS.
#define S1 76    // A1 / W1T row stride (K=72 padded)
#define S2 132   // A2 / W2T row stride (K=128 padded)
#define W1T_OFF 0
#define W2T_OFF (128*S1)
#define A1_OFF  (W2T_OFF + 128*S2)
#define A2_OFF  (A1_OFF + 128*S1)
#define SMEM_FLOATS (A2_OFF + 128*S2)   // 53248 floats = 212992 B

// ---------------- device scratch ----------------
__device__ int g_fps[NCTR];
__device__ int g_prog[NB];      // per-cloud produced-center count
__device__ int g_tile_ctr;

// ---------------- helpers ----------------
__device__ __forceinline__ float dist2(float ax,float ay,float az,float bx,float by,float bz){
    float dx = ax - bx, dy = ay - by, dz = az - bz;
    return __fadd_rn(__fadd_rn(__fmul_rn(dx,dx), __fmul_rn(dy,dy)), __fmul_rn(dz,dz));
}
__device__ __forceinline__ float rna_tf32(float f){
    float o; asm("cvt.rna.tf32.f32 %0, %1;" : "=f"(o) : "f"(f)); return o;
}
__device__ __forceinline__ void st_rel(int* a, int v){
    asm volatile("st.release.gpu.global.s32 [%0], %1;" :: "l"(a), "r"(v) : "memory");
}
__device__ __forceinline__ int ld_acq(const int* a){
    int v; asm volatile("ld.acquire.gpu.global.s32 %0, [%1];" : "=r"(v) : "l"(a) : "memory");
    return v;
}

// ---- packed f32x2 (Blackwell base ISA; per-lane IEEE rn => bit-exact) ----
__device__ __forceinline__ uint64_t pack2(float lo, float hi){
    uint64_t r; asm("mov.b64 %0, {%1,%2};" : "=l"(r) : "f"(lo), "f"(hi)); return r;
}
__device__ __forceinline__ void unpack2(uint64_t v, float& lo, float& hi){
    asm("mov.b64 {%0,%1}, %2;" : "=f"(lo), "=f"(hi) : "l"(v));
}
#define SUB2(o,a,b) asm("sub.rn.f32x2 %0, %1, %2;" : "=l"(o) : "l"(a), "l"(b))
#define MUL2(o,a,b) asm("mul.rn.f32x2 %0, %1, %2;" : "=l"(o) : "l"(a), "l"(b))
#define ADD2(o,a,b) asm("add.rn.f32x2 %0, %1, %2;" : "=l"(o) : "l"(a), "l"(b))

#define MMA_TF32(d, a, b) \
    asm volatile("mma.sync.aligned.m16n8k8.row.col.f32.tf32.tf32.f32 " \
        "{%0,%1,%2,%3}, {%4,%5,%6,%7}, {%8,%9}, {%0,%1,%2,%3};" \
        : "+f"((d)[0]), "+f"((d)[1]), "+f"((d)[2]), "+f"((d)[3]) \
        : "r"((a)[0]), "r"((a)[1]), "r"((a)[2]), "r"((a)[3]), \
          "r"((b)[0]), "r"((b)[1]))

// ---------------------------------------------------------------------------
__global__ void init_kernel(){
    if (threadIdx.x == 0) g_tile_ctr = 0;
    if (threadIdx.x < NB) g_prog[threadIdx.x] = 0;
}

// ---------------------------------------------------------------------------
// Per-warp GEMM: 16 rows x 32 cols via 1x4 grid of m16n8k8 tf32 mma.sync.
// ---------------------------------------------------------------------------
template<int KSTEPS, int SA, int SB>
__device__ __forceinline__ void gemm_tile16(const float* __restrict__ As,
                                            const float* __restrict__ Bs,
                                            int warpR, int warpC, int g, int tg,
                                            float acc[4][4]){
    const uint32_t* Au = (const uint32_t*)As;
    const uint32_t* Bu = (const uint32_t*)Bs;
#pragma unroll 1
    for (int ks = 0; ks < KSTEPS; ++ks){
        int k0 = ks*8 + tg;
        uint32_t a[4], bf[4][2];
        const uint32_t* ar = Au + (warpR + g)*SA + k0;
        a[0] = ar[0];
        a[1] = ar[8*SA];
        a[2] = ar[4];
        a[3] = ar[8*SA + 4];
#pragma unroll
        for (int nt = 0; nt < 4; ++nt){
            const uint32_t* br = Bu + (warpC + nt*8 + g)*SB + k0;
            bf[nt][0] = br[0];
            bf[nt][1] = br[4];
        }
#pragma unroll
        for (int nt = 0; nt < 4; ++nt)
            MMA_TF32(acc[nt], a, bf[nt]);
    }
}

// ---------------------------------------------------------------------------
// Fused kernel: 148 blocks x 1024 threads, all co-resident (1 block/SM).
// ---------------------------------------------------------------------------
__global__ void __launch_bounds__(1024,1) fused_kernel(
        const float* __restrict__ x,  const float* __restrict__ pos,
        const float* __restrict__ W1, const float* __restrict__ b1,
        const float* __restrict__ W2, const float* __restrict__ b2,
        float* __restrict__ out, int out_size){
    extern __shared__ float sm[];
    float* W1s = sm + W1T_OFF;
    float* W2s = sm + W2T_OFF;
    float* A1s = sm + A1_OFF;
    float* A2s = sm + A2_OFF;

    __shared__ unsigned sv[2][16], si[2][16];    // FPS cross-warp stage (16 active warps)
    __shared__ int s_tile;
    __shared__ int s_cnt[2], s_M[2], s_nb[2][KNBR];
    __shared__ unsigned aggU[256];               // column-max agg (float bits, >=0)
    __shared__ float bbs[256];                   // b1 | b2

    int tid = threadIdx.x, w = tid >> 5, lane = tid & 31;
    const unsigned FULL = 0xffffffffu;

    // ======================= producer: FPS (blocks 0-7) =======================
    if (blockIdx.x < NB){
        int b = blockIdx.x;
        const float* p = pos + (size_t)b * NPER * 3;
        bool act = tid < 512;

        // 8 points/thread as 4 packed pairs: pair q = points (tid+2q*512, tid+(2q+1)*512)
        uint64_t PX[4], PY[4], PZ[4];
        float md[8];
        if (act){
#pragma unroll
            for (int q = 0; q < 4; ++q){
                int i0 = tid + (2*q)*512, i1 = tid + (2*q+1)*512;
                PX[q] = pack2(p[i0*3+0], p[i1*3+0]);
                PY[q] = pack2(p[i0*3+1], p[i1*3+1]);
                PZ[q] = pack2(p[i0*3+2], p[i1*3+2]);
                md[2*q] = 1e10f; md[2*q+1] = 1e10f;
            }
        }
        float cx = p[0], cy = p[1], cz = p[2];
        if (tid == 0) g_fps[b*NS] = 0;
        __syncthreads();

        for (int s = 1; s < NS; ++s){
            if (act){
                uint64_t CX2 = pack2(cx, cx), CY2 = pack2(cy, cy), CZ2 = pack2(cz, cz);
#pragma unroll
                for (int q = 0; q < 4; ++q){
                    uint64_t dx, dy, dz, xx, yy, zz, ss;
                    SUB2(dx, PX[q], CX2);
                    SUB2(dy, PY[q], CY2);
                    SUB2(dz, PZ[q], CZ2);
                    MUL2(xx, dx, dx);
                    MUL2(yy, dy, dy);
                    MUL2(zz, dz, dz);
                    ADD2(ss, xx, yy);
                    ADD2(ss, ss, zz);
                    float d0, d1; unpack2(ss, d0, d1);
                    md[2*q]   = fminf(md[2*q],   d0);
                    md[2*q+1] = fminf(md[2*q+1], d1);
                }
                float tv = fmaxf(fmaxf(fmaxf(md[0], md[1]), fmaxf(md[2], md[3])),
                                 fmaxf(fmaxf(md[4], md[5]), fmaxf(md[6], md[7])));

                unsigned wv = __reduce_max_sync(FULL, __float_as_uint(tv));
                unsigned mi = 0xFFFFFFFFu;
                if (__float_as_uint(tv) == wv){      // rare: only winning thread(s) search
#pragma unroll
                    for (int j = 0; j < 8; ++j){
                        unsigned gi = (unsigned)(tid + j*512);
                        if (__float_as_uint(md[j]) == wv) mi = min(mi, gi);
                    }
                }
                unsigned wi = __reduce_min_sync(FULL, mi);

                int par = s & 1;
                if (lane == 0){ sv[par][w] = wv; si[par][w] = wi; }
            }
            __syncthreads();

            if (act){
                int par = s & 1;
                unsigned lv = (lane < 16) ? sv[par][lane] : 0u;
                unsigned gv = __reduce_max_sync(FULL, lv);
                unsigned cand = (lane < 16 && lv == gv) ? si[par][lane] : 0xFFFFFFFFu;
                unsigned gidx = __reduce_min_sync(FULL, cand);

                if (tid == 0){
                    g_fps[b*NS + s] = (int)gidx;
                    if ((s & 3) == 3) st_rel(&g_prog[b], s + 1);   // publish every 4
                }
                cx = p[gidx*3+0]; cy = p[gidx*3+1]; cz = p[gidx*3+2];
            }
        }
        __syncthreads();
    }

    // ======================= consumer: all blocks =======================
    // stage weights (transpose + tf32-round) + biases
    for (int i = tid; i < 67*HDIM; i += 1024){
        int k = i >> 7, n = i & 127;
        W1s[n*S1 + k] = rna_tf32(W1[i]);
    }
    for (int i = tid; i < 128*5; i += 1024){          // zero pad k=67..71
        int n = i / 5, k = 67 + i % 5;
        W1s[n*S1 + k] = 0.f;
    }
    for (int i = tid; i < HDIM*HDIM; i += 1024){
        int k = i >> 7, n = i & 127;
        W2s[n*S2 + k] = rna_tf32(W2[i]);
    }
    if (tid < 128){ bbs[tid] = b1[tid]; bbs[128 + tid] = b2[tid]; }
    if (tid < 256) aggU[tid] = 0u;

    int g = lane >> 2, tg = lane & 3;
    int warpR = (w >> 2) * 16;     // 8 row-groups of 16 rows
    int warpC = (w & 3) * 32;      // 4 column blocks
    int center = warpR >> 6;       // 0 or 1
    __syncthreads();

    for (;;){
        if (tid == 0) s_tile = atomicAdd(&g_tile_ctr, 1);
        __syncthreads();
        int ticket = s_tile;
        if (ticket >= NTILES) break;
        int cloud = ticket & 7, pair = ticket >> 3;
        int c0 = cloud*NS + pair*2;

        // wait until both centers of this tile exist
        if (tid == 0){
            int need = pair*2 + 2, bo = 32;
            while (ld_acq(&g_prog[cloud]) < need){
                __nanosleep(bo);
                if (bo < 1024) bo <<= 1;
            }
        }
        __syncthreads();

        const float* p = pos + (size_t)cloud * NPER * 3;
        size_t base = (size_t)cloud * NPER;

        // ---- inlined select: 2 groups of 512 threads, one center each ----
        int grp = tid >> 9, lt = tid & 511;
        int ci = c0 + grp;
        int cidx = g_fps[ci];
        float cx = p[cidx*3+0], cy = p[cidx*3+1], cz = p[cidx*3+2];
        float* cdg = A2s + grp*CAP;
        int*   cig = ((int*)A2s) + 2*CAP + grp*CAP;
        if (lt == 0) s_cnt[grp] = 0;
        __syncthreads();

        for (int i = lt; i < NPER; i += 512){
            float d = dist2(p[i*3+0], p[i*3+1], p[i*3+2], cx, cy, cz);
            if (d <= R2){
                int q = atomicAdd(&s_cnt[grp], 1);
                if (q < CAP){ cdg[q] = d; cig[q] = i; }
            }
        }
        __syncthreads();
        int m = min(s_cnt[grp], CAP);
        if (m <= KNBR){
            for (int j = lt; j < m; j += 512) s_nb[grp][j] = cig[j];
            if (lt == 0) s_M[grp] = m;
        } else {
            for (int j = lt; j < m; j += 512){
                float dj = cdg[j]; int ij = cig[j];
                int r = 0;
                for (int u = 0; u < m; ++u){
                    float du = cdg[u];
                    r += (du < dj) || (du == dj && cig[u] < ij);
                }
                if (r < KNBR) s_nb[grp][r] = ij;
            }
            if (lt == 0) s_M[grp] = KNBR;
        }
        if (lt == 0 && out_size >= NCTR*HDIM + NCTR*3 + NCTR){
            float* po = out + NCTR*HDIM;
            po[ci*3+0] = cx; po[ci*3+1] = cy; po[ci*3+2] = cz;
            out[NCTR*HDIM + NCTR*3 + ci] = (float)cloud;
        }
        __syncthreads();
        int M0 = s_M[0], M1 = s_M[1];

        // ---- gather A1 [128 x 72] (tf32-rounded, zero-padded); 8 thr/row ----
        {
            int r = tid >> 3, q = tid & 7;
            int rg = r >> 6; int sl = r & 63;
            int M = rg ? M1 : M0;
            bool v = sl < M;
            float* arow = A1s + r*S1;
            const float4* xr = nullptr;
            int gl = 0;
            if (v){
                gl = s_nb[rg][sl];
                xr = (const float4*)(x + (base + gl)*CIN);
            }
            float4 t = v ? xr[q] : make_float4(0,0,0,0);
            t.x = rna_tf32(t.x); t.y = rna_tf32(t.y);
            t.z = rna_tf32(t.z); t.w = rna_tf32(t.w);
            *(float4*)(arow + 4*q) = t;
            t = v ? xr[q+8] : make_float4(0,0,0,0);
            t.x = rna_tf32(t.x); t.y = rna_tf32(t.y);
            t.z = rna_tf32(t.z); t.w = rna_tf32(t.w);
            *(float4*)(arow + 4*q + 32) = t;
            if (q == 0){
                float4 d4 = make_float4(0,0,0,0);
                if (v){
                    const float* pr = p + gl*3;
                    const float* pc = p + g_fps[c0 + rg]*3;
                    d4.x = rna_tf32(pr[0] - pc[0]);
                    d4.y = rna_tf32(pr[1] - pc[1]);
                    d4.z = rna_tf32(pr[2] - pc[2]);
                }
                *(float4*)(arow + 64) = d4;
            } else if (q == 1){
                *(float4*)(arow + 68) = make_float4(0,0,0,0);
            }
        }
        __syncthreads();

        // ---- GEMM1: [128x72] @ W1T -> relu+round -> A2 ----
        float acc[4][4];
#pragma unroll
        for (int nt = 0; nt < 4; ++nt)
#pragma unroll
            for (int i = 0; i < 4; ++i) acc[nt][i] = 0.f;
        gemm_tile16<9, S1, S1>(A1s, W1s, warpR, warpC, g, tg, acc);

        {
            int r0 = warpR + g;
#pragma unroll
            for (int nt = 0; nt < 4; ++nt){
                int cc = warpC + nt*8 + 2*tg;
                float ba = bbs[cc], bb = bbs[cc+1];
                float* d = acc[nt];
                float2 h0, h1;
                h0.x = rna_tf32(fmaxf(d[0] + ba, 0.f));
                h0.y = rna_tf32(fmaxf(d[1] + bb, 0.f));
                h1.x = rna_tf32(fmaxf(d[2] + ba, 0.f));
                h1.y = rna_tf32(fmaxf(d[3] + bb, 0.f));
                *(float2*)&A2s[r0*S2 + cc]     = h0;
                *(float2*)&A2s[(r0+8)*S2 + cc] = h1;
            }
        }
        __syncthreads();

        // ---- GEMM2: [128x128] @ W2T, fused relu + masked max ----
#pragma unroll
        for (int nt = 0; nt < 4; ++nt)
#pragma unroll
            for (int i = 0; i < 4; ++i) acc[nt][i] = 0.f;
        gemm_tile16<16, S2, S2>(A2s, W2s, warpR, warpC, g, tg, acc);

        {
            int M = center ? M1 : M0;
            int rIn = (warpR & 63) + g;
            bool v0 = rIn < M, v1 = (rIn + 8) < M;
            float cm[8];
#pragma unroll
            for (int i = 0; i < 8; ++i) cm[i] = 0.f;   // valid contributions are >= 0
#pragma unroll
            for (int nt = 0; nt < 4; ++nt){
                int cc = warpC + nt*8 + 2*tg;
                float ba = bbs[128+cc], bb = bbs[128+cc+1];
                float* d = acc[nt];
                if (v0){
                    cm[nt*2]   = fmaxf(cm[nt*2],   fmaxf(d[0] + ba, 0.f));
                    cm[nt*2+1] = fmaxf(cm[nt*2+1], fmaxf(d[1] + bb, 0.f));
                }
                if (v1){
                    cm[nt*2]   = fmaxf(cm[nt*2],   fmaxf(d[2] + ba, 0.f));
                    cm[nt*2+1] = fmaxf(cm[nt*2+1], fmaxf(d[3] + bb, 0.f));
                }
            }
#pragma unroll
            for (int o = 16; o >= 4; o >>= 1)
#pragma unroll
                for (int i = 0; i < 8; ++i)
                    cm[i] = fmaxf(cm[i], __shfl_down_sync(FULL, cm[i], o));
            if (lane < 4){       // g==0 lanes hold warp-level col maxima (tg=lane)
#pragma unroll
                for (int nt = 0; nt < 4; ++nt){
                    int cc = warpC + nt*8 + 2*lane;
                    atomicMax(&aggU[center*128 + cc],     __float_as_uint(cm[nt*2]));
                    atomicMax(&aggU[center*128 + cc + 1], __float_as_uint(cm[nt*2+1]));
                }
            }
        }
        __syncthreads();

        if (tid < 256){
            int cen = tid >> 7, col = tid & 127;
            out[(size_t)(c0 + cen)*HDIM + col] = __uint_as_float(aggU[tid]);
            aggU[tid] = 0u;      // reset for next ticket (same thread -> no race)
        }
    }
}

// ---------------------------------------------------------------------------
extern "C" void kernel_launch(void* const* d_in, const int* in_sizes, int n_in,
                              void* d_out, int out_size){
    const float *x = 0, *pos = 0, *W1 = 0, *b1 = 0, *W2 = 0, *b2 = 0;
    for (int i = 0; i < n_in; ++i){
        int s = in_sizes[i];
        const float* p = (const float*)d_in[i];
        if      (s == NB*NPER*CIN)  x   = p;
        else if (s == NB*NPER*3)    pos = p;
        else if (s == 67*HDIM)      W1  = p;
        else if (s == HDIM*HDIM)    W2  = p;
        else if (s == HDIM){ if (!b1) b1 = p; else b2 = p; }
    }
    float* out = (float*)d_out;

    size_t smem = SMEM_FLOATS * sizeof(float);
    cudaFuncSetAttribute(fused_kernel, cudaFuncAttributeMaxDynamicSharedMemorySize, (int)smem);

    init_kernel<<<1, 32>>>();
    fused_kernel<<<148, 1024, smem>>>(x, pos, W1, b1, W2, b2, out, out_size);
}

// round 15
// speedup vs baseline: 1.1360x; 1.1360x over previous
#include <cuda_runtime.h>
#include <cstdint>

// PointNet++ SA layer, fused producer/consumer, 1024-thread blocks:
//   blocks 0-7: FPS (1024 thr, 4 pts/thr, packed f32x2 math) streaming centers
//   all blocks: persistent consumers (ball query + tf32 mma.sync MLP + max agg)
#define NB    8
#define NPER  4096
#define NS    1024
#define KNBR  64
#define CIN   64
#define HDIM  128
#define NCTR  (NB*NPER/4)  // 8192
#define NTILES (NCTR/2)    // 4096 tiles of 128 rows (2 centers x 64 slots)
#define CAP   1024
#define R2    0.04f

// SMEM strides (floats). Chosen for conflict-free mma fragment LDS.
#define S1 76    // A1 / W1T row stride (K=72 padded)
#define S2 132   // A2 / W2T row stride (K=128 padded)
#define W1T_OFF 0
#define W2T_OFF (128*S1)
#define A1_OFF  (W2T_OFF + 128*S2)
#define A2_OFF  (A1_OFF + 128*S1)
#define SMEM_FLOATS (A2_OFF + 128*S2)   // 53248 floats = 212992 B

// ---------------- device scratch ----------------
__device__ int g_fps[NCTR];
__device__ int g_prog[NB];      // per-cloud produced-center count
__device__ int g_tile_ctr;

// ---------------- helpers ----------------
__device__ __forceinline__ float dist2(float ax,float ay,float az,float bx,float by,float bz){
    float dx = ax - bx, dy = ay - by, dz = az - bz;
    return __fadd_rn(__fadd_rn(__fmul_rn(dx,dx), __fmul_rn(dy,dy)), __fmul_rn(dz,dz));
}
__device__ __forceinline__ float rna_tf32(float f){
    float o; asm("cvt.rna.tf32.f32 %0, %1;" : "=f"(o) : "f"(f)); return o;
}
__device__ __forceinline__ void st_rel(int* a, int v){
    asm volatile("st.release.gpu.global.s32 [%0], %1;" :: "l"(a), "r"(v) : "memory");
}
__device__ __forceinline__ int ld_acq(const int* a){
    int v; asm volatile("ld.acquire.gpu.global.s32 %0, [%1];" : "=r"(v) : "l"(a) : "memory");
    return v;
}

// ---- packed f32x2 (Blackwell base ISA; per-lane IEEE rn => bit-exact) ----
__device__ __forceinline__ uint64_t pack2(float lo, float hi){
    uint64_t r; asm("mov.b64 %0, {%1,%2};" : "=l"(r) : "f"(lo), "f"(hi)); return r;
}
__device__ __forceinline__ void unpack2(uint64_t v, float& lo, float& hi){
    asm("mov.b64 {%0,%1}, %2;" : "=f"(lo), "=f"(hi) : "l"(v));
}
#define SUB2(o,a,b) asm("sub.rn.f32x2 %0, %1, %2;" : "=l"(o) : "l"(a), "l"(b))
#define MUL2(o,a,b) asm("mul.rn.f32x2 %0, %1, %2;" : "=l"(o) : "l"(a), "l"(b))
#define ADD2(o,a,b) asm("add.rn.f32x2 %0, %1, %2;" : "=l"(o) : "l"(a), "l"(b))

#define MMA_TF32(d, a, b) \
    asm volatile("mma.sync.aligned.m16n8k8.row.col.f32.tf32.tf32.f32 " \
        "{%0,%1,%2,%3}, {%4,%5,%6,%7}, {%8,%9}, {%0,%1,%2,%3};" \
        : "+f"((d)[0]), "+f"((d)[1]), "+f"((d)[2]), "+f"((d)[3]) \
        : "r"((a)[0]), "r"((a)[1]), "r"((a)[2]), "r"((a)[3]), \
          "r"((b)[0]), "r"((b)[1]))

// ---------------------------------------------------------------------------
__global__ void init_kernel(){
    if (threadIdx.x == 0) g_tile_ctr = 0;
    if (threadIdx.x < NB) g_prog[threadIdx.x] = 0;
}

// ---------------------------------------------------------------------------
// Per-warp GEMM: 16 rows x 32 cols via 1x4 grid of m16n8k8 tf32 mma.sync.
// ---------------------------------------------------------------------------
template<int KSTEPS, int SA, int SB>
__device__ __forceinline__ void gemm_tile16(const float* __restrict__ As,
                                            const float* __restrict__ Bs,
                                            int warpR, int warpC, int g, int tg,
                                            float acc[4][4]){
    const uint32_t* Au = (const uint32_t*)As;
    const uint32_t* Bu = (const uint32_t*)Bs;
#pragma unroll 1
    for (int ks = 0; ks < KSTEPS; ++ks){
        int k0 = ks*8 + tg;
        uint32_t a[4], bf[4][2];
        const uint32_t* ar = Au + (warpR + g)*SA + k0;
        a[0] = ar[0];
        a[1] = ar[8*SA];
        a[2] = ar[4];
        a[3] = ar[8*SA + 4];
#pragma unroll
        for (int nt = 0; nt < 4; ++nt){
            const uint32_t* br = Bu + (warpC + nt*8 + g)*SB + k0;
            bf[nt][0] = br[0];
            bf[nt][1] = br[4];
        }
#pragma unroll
        for (int nt = 0; nt < 4; ++nt)
            MMA_TF32(acc[nt], a, bf[nt]);
    }
}

// ---------------------------------------------------------------------------
// Fused kernel: 148 blocks x 1024 threads, all co-resident (1 block/SM).
// ---------------------------------------------------------------------------
__global__ void __launch_bounds__(1024,1) fused_kernel(
        const float* __restrict__ x,  const float* __restrict__ pos,
        const float* __restrict__ W1, const float* __restrict__ b1,
        const float* __restrict__ W2, const float* __restrict__ b2,
        float* __restrict__ out, int out_size){
    extern __shared__ float sm[];
    float* W1s = sm + W1T_OFF;
    float* W2s = sm + W2T_OFF;
    float* A1s = sm + A1_OFF;
    float* A2s = sm + A2_OFF;

    __shared__ unsigned sv[2][32], si[2][32];    // FPS cross-warp stage
    __shared__ int s_tile;
    __shared__ int s_cnt[2], s_M[2], s_nb[2][KNBR];
    __shared__ unsigned aggU[256];               // column-max agg (float bits, >=0)
    __shared__ float bbs[256];                   // b1 | b2

    int tid = threadIdx.x, w = tid >> 5, lane = tid & 31;
    const unsigned FULL = 0xffffffffu;

    // ======================= producer: FPS (blocks 0-7) =======================
    if (blockIdx.x < NB){
        int b = blockIdx.x;
        const float* p = pos + (size_t)b * NPER * 3;

        // 4 points/thread as 2 packed pairs: pair q holds points (tid+2q*1024, tid+(2q+1)*1024)
        uint64_t PX[2], PY[2], PZ[2];
        float md[4];
#pragma unroll
        for (int q = 0; q < 2; ++q){
            int i0 = tid + (2*q)*1024, i1 = tid + (2*q+1)*1024;
            PX[q] = pack2(p[i0*3+0], p[i1*3+0]);
            PY[q] = pack2(p[i0*3+1], p[i1*3+1]);
            PZ[q] = pack2(p[i0*3+2], p[i1*3+2]);
            md[2*q] = 1e10f; md[2*q+1] = 1e10f;
        }
        float cx = p[0], cy = p[1], cz = p[2];
        if (tid == 0) g_fps[b*NS] = 0;
        __syncthreads();

        for (int s = 1; s < NS; ++s){
            uint64_t CX2 = pack2(cx, cx), CY2 = pack2(cy, cy), CZ2 = pack2(cz, cz);
#pragma unroll
            for (int q = 0; q < 2; ++q){
                uint64_t dx, dy, dz, xx, yy, zz, ss;
                SUB2(dx, PX[q], CX2);
                SUB2(dy, PY[q], CY2);
                SUB2(dz, PZ[q], CZ2);
                MUL2(xx, dx, dx);
                MUL2(yy, dy, dy);
                MUL2(zz, dz, dz);
                ADD2(ss, xx, yy);
                ADD2(ss, ss, zz);
                float d0, d1; unpack2(ss, d0, d1);
                md[2*q]   = fminf(md[2*q],   d0);
                md[2*q+1] = fminf(md[2*q+1], d1);
            }
            float tv = fmaxf(fmaxf(md[0], md[1]), fmaxf(md[2], md[3]));

            unsigned wv = __reduce_max_sync(FULL, __float_as_uint(tv));
            unsigned mi = 0xFFFFFFFFu;
            if (__float_as_uint(tv) == wv){      // rare: only winning thread(s) search
#pragma unroll
                for (int j = 0; j < 4; ++j){
                    unsigned gi = (unsigned)(tid + j*1024);
                    if (__float_as_uint(md[j]) == wv) mi = min(mi, gi);
                }
            }
            unsigned wi = __reduce_min_sync(FULL, mi);

            int par = s & 1;
            if (lane == 0){ sv[par][w] = wv; si[par][w] = wi; }
            __syncthreads();

            unsigned lv = sv[par][lane];
            unsigned gv = __reduce_max_sync(FULL, lv);
            unsigned cand = (lv == gv) ? si[par][lane] : 0xFFFFFFFFu;
            unsigned gidx = __reduce_min_sync(FULL, cand);

            if (tid == 0){
                g_fps[b*NS + s] = (int)gidx;
                if ((s & 3) == 3) st_rel(&g_prog[b], s + 1);   // publish every 4
            }
            cx = p[gidx*3+0]; cy = p[gidx*3+1]; cz = p[gidx*3+2];
        }
        __syncthreads();
    }

    // ======================= consumer: all blocks =======================
    // stage weights (transpose + tf32-round) + biases
    for (int i = tid; i < 67*HDIM; i += 1024){
        int k = i >> 7, n = i & 127;
        W1s[n*S1 + k] = rna_tf32(W1[i]);
    }
    for (int i = tid; i < 128*5; i += 1024){          // zero pad k=67..71
        int n = i / 5, k = 67 + i % 5;
        W1s[n*S1 + k] = 0.f;
    }
    for (int i = tid; i < HDIM*HDIM; i += 1024){
        int k = i >> 7, n = i & 127;
        W2s[n*S2 + k] = rna_tf32(W2[i]);
    }
    if (tid < 128){ bbs[tid] = b1[tid]; bbs[128 + tid] = b2[tid]; }
    if (tid < 256) aggU[tid] = 0u;

    int g = lane >> 2, tg = lane & 3;
    int warpR = (w >> 2) * 16;     // 8 row-groups of 16 rows
    int warpC = (w & 3) * 32;      // 4 column blocks
    int center = warpR >> 6;       // 0 or 1
    __syncthreads();

    for (;;){
        if (tid == 0) s_tile = atomicAdd(&g_tile_ctr, 1);
        __syncthreads();
        int ticket = s_tile;
        if (ticket >= NTILES) break;
        int cloud = ticket & 7, pair = ticket >> 3;
        int c0 = cloud*NS + pair*2;

        // wait until both centers of this tile exist
        if (tid == 0){
            int need = pair*2 + 2, bo = 32;
            while (ld_acq(&g_prog[cloud]) < need){
                __nanosleep(bo);
                if (bo < 4096) bo <<= 1;
            }
        }
        __syncthreads();

        const float* p = pos + (size_t)cloud * NPER * 3;
        size_t base = (size_t)cloud * NPER;

        // ---- inlined select: 2 groups of 512 threads, one center each ----
        int grp = tid >> 9, lt = tid & 511;
        int ci = c0 + grp;
        int cidx = g_fps[ci];
        float cx = p[cidx*3+0], cy = p[cidx*3+1], cz = p[cidx*3+2];
        float* cdg = A2s + grp*CAP;
        int*   cig = ((int*)A2s) + 2*CAP + grp*CAP;
        if (lt == 0) s_cnt[grp] = 0;
        __syncthreads();

        for (int i = lt; i < NPER; i += 512){
            float d = dist2(p[i*3+0], p[i*3+1], p[i*3+2], cx, cy, cz);
            if (d <= R2){
                int q = atomicAdd(&s_cnt[grp], 1);
                if (q < CAP){ cdg[q] = d; cig[q] = i; }
            }
        }
        __syncthreads();
        int m = min(s_cnt[grp], CAP);
        if (m <= KNBR){
            for (int j = lt; j < m; j += 512) s_nb[grp][j] = cig[j];
            if (lt == 0) s_M[grp] = m;
        } else {
            for (int j = lt; j < m; j += 512){
                float dj = cdg[j]; int ij = cig[j];
                int r = 0;
                for (int u = 0; u < m; ++u){
                    float du = cdg[u];
                    r += (du < dj) || (du == dj && cig[u] < ij);
                }
                if (r < KNBR) s_nb[grp][r] = ij;
            }
            if (lt == 0) s_M[grp] = KNBR;
        }
        if (lt == 0 && out_size >= NCTR*HDIM + NCTR*3 + NCTR){
            float* po = out + NCTR*HDIM;
            po[ci*3+0] = cx; po[ci*3+1] = cy; po[ci*3+2] = cz;
            out[NCTR*HDIM + NCTR*3 + ci] = (float)cloud;
        }
        __syncthreads();
        int M0 = s_M[0], M1 = s_M[1];

        // ---- gather A1 [128 x 72] (tf32-rounded, zero-padded); 8 thr/row ----
        {
            int r = tid >> 3, q = tid & 7;
            int rg = r >> 6; int sl = r & 63;
            int M = rg ? M1 : M0;
            bool v = sl < M;
            float* arow = A1s + r*S1;
            const float4* xr = nullptr;
            int gl = 0;
            if (v){
                gl = s_nb[rg][sl];
                xr = (const float4*)(x + (base + gl)*CIN);
            }
            float4 t = v ? xr[q] : make_float4(0,0,0,0);
            t.x = rna_tf32(t.x); t.y = rna_tf32(t.y);
            t.z = rna_tf32(t.z); t.w = rna_tf32(t.w);
            *(float4*)(arow + 4*q) = t;
            t = v ? xr[q+8] : make_float4(0,0,0,0);
            t.x = rna_tf32(t.x); t.y = rna_tf32(t.y);
            t.z = rna_tf32(t.z); t.w = rna_tf32(t.w);
            *(float4*)(arow + 4*q + 32) = t;
            if (q == 0){
                float4 d4 = make_float4(0,0,0,0);
                if (v){
                    const float* pr = p + gl*3;
                    const float* pc = p + g_fps[c0 + rg]*3;
                    d4.x = rna_tf32(pr[0] - pc[0]);
                    d4.y = rna_tf32(pr[1] - pc[1]);
                    d4.z = rna_tf32(pr[2] - pc[2]);
                }
                *(float4*)(arow + 64) = d4;
            } else if (q == 1){
                *(float4*)(arow + 68) = make_float4(0,0,0,0);
            }
        }
        __syncthreads();

        // ---- GEMM1: [128x72] @ W1T -> relu+round -> A2 ----
        float acc[4][4];
#pragma unroll
        for (int nt = 0; nt < 4; ++nt)
#pragma unroll
            for (int i = 0; i < 4; ++i) acc[nt][i] = 0.f;
        gemm_tile16<9, S1, S1>(A1s, W1s, warpR, warpC, g, tg, acc);

        {
            int r0 = warpR + g;
#pragma unroll
            for (int nt = 0; nt < 4; ++nt){
                int cc = warpC + nt*8 + 2*tg;
                float ba = bbs[cc], bb = bbs[cc+1];
                float* d = acc[nt];
                float2 h0, h1;
                h0.x = rna_tf32(fmaxf(d[0] + ba, 0.f));
                h0.y = rna_tf32(fmaxf(d[1] + bb, 0.f));
                h1.x = rna_tf32(fmaxf(d[2] + ba, 0.f));
                h1.y = rna_tf32(fmaxf(d[3] + bb, 0.f));
                *(float2*)&A2s[r0*S2 + cc]     = h0;
                *(float2*)&A2s[(r0+8)*S2 + cc] = h1;
            }
        }
        __syncthreads();

        // ---- GEMM2: [128x128] @ W2T, fused relu + masked max ----
#pragma unroll
        for (int nt = 0; nt < 4; ++nt)
#pragma unroll
            for (int i = 0; i < 4; ++i) acc[nt][i] = 0.f;
        gemm_tile16<16, S2, S2>(A2s, W2s, warpR, warpC, g, tg, acc);

        {
            int M = center ? M1 : M0;
            int rIn = (warpR & 63) + g;
            bool v0 = rIn < M, v1 = (rIn + 8) < M;
            float cm[8];
#pragma unroll
            for (int i = 0; i < 8; ++i) cm[i] = 0.f;   // valid contributions are >= 0
#pragma unroll
            for (int nt = 0; nt < 4; ++nt){
                int cc = warpC + nt*8 + 2*tg;
                float ba = bbs[128+cc], bb = bbs[128+cc+1];
                float* d = acc[nt];
                if (v0){
                    cm[nt*2]   = fmaxf(cm[nt*2],   fmaxf(d[0] + ba, 0.f));
                    cm[nt*2+1] = fmaxf(cm[nt*2+1], fmaxf(d[1] + bb, 0.f));
                }
                if (v1){
                    cm[nt*2]   = fmaxf(cm[nt*2],   fmaxf(d[2] + ba, 0.f));
                    cm[nt*2+1] = fmaxf(cm[nt*2+1], fmaxf(d[3] + bb, 0.f));
                }
            }
#pragma unroll
            for (int o = 16; o >= 4; o >>= 1)
#pragma unroll
                for (int i = 0; i < 8; ++i)
                    cm[i] = fmaxf(cm[i], __shfl_down_sync(FULL, cm[i], o));
            if (lane < 4){       // g==0 lanes hold warp-level col maxima (tg=lane)
#pragma unroll
                for (int nt = 0; nt < 4; ++nt){
                    int cc = warpC + nt*8 + 2*lane;
                    atomicMax(&aggU[center*128 + cc],     __float_as_uint(cm[nt*2]));
                    atomicMax(&aggU[center*128 + cc + 1], __float_as_uint(cm[nt*2+1]));
                }
            }
        }
        __syncthreads();

        if (tid < 256){
            int cen = tid >> 7, col = tid & 127;
            out[(size_t)(c0 + cen)*HDIM + col] = __uint_as_float(aggU[tid]);
            aggU[tid] = 0u;      // reset for next ticket (same thread -> no race)
        }
    }
}

// ---------------------------------------------------------------------------
extern "C" void kernel_launch(void* const* d_in, const int* in_sizes, int n_in,
                              void* d_out, int out_size){
    const float *x = 0, *pos = 0, *W1 = 0, *b1 = 0, *W2 = 0, *b2 = 0;
    for (int i = 0; i < n_in; ++i){
        int s = in_sizes[i];
        const float* p = (const float*)d_in[i];
        if      (s == NB*NPER*CIN)  x   = p;
        else if (s == NB*NPER*3)    pos = p;
        else if (s == 67*HDIM)      W1  = p;
        else if (s == HDIM*HDIM)    W2  = p;
        else if (s == HDIM){ if (!b1) b1 = p; else b2 = p; }
    }
    float* out = (float*)d_out;

    size_t smem = SMEM_FLOATS * sizeof(float);
    cudaFuncSetAttribute(fused_kernel, cudaFuncAttributeMaxDynamicSharedMemorySize, (int)smem);

    init_kernel<<<1, 32>>>();
    fused_kernel<<<148, 1024, smem>>>(x, pos, W1, b1, W2, b2, out, out_size);
}

// round 16
// speedup vs baseline: 1.2000x; 1.0563x over previous
#include <cuda_runtime.h>
#include <cstdint>

// PointNet++ SA layer, fused producer/consumer, 1024-thread blocks:
//   blocks 0-7: FPS w/ exact warp-bucket skip (spatial sort + AABB bound)
//   all blocks: persistent consumers (ball query + tf32 mma.sync MLP + max agg)
#define NB    8
#define NPER  4096
#define NS    1024
#define KNBR  64
#define CIN   64
#define HDIM  128
#define NCTR  (NB*NPER/4)  // 8192
#define NTILES (NCTR/2)    // 4096 tiles of 128 rows (2 centers x 64 slots)
#define CAP   1024
#define R2    0.04f

// SMEM strides (floats). Chosen for conflict-free mma fragment LDS.
#define S1 76    // A1 / W1T row stride (K=72 padded)
#define S2 132   // A2 / W2T row stride (K=128 padded)
#define W1T_OFF 0
#define W2T_OFF (128*S1)
#define A1_OFF  (W2T_OFF + 128*S2)
#define A2_OFF  (A1_OFF + 128*S1)
#define SMEM_FLOATS (A2_OFF + 128*S2)   // 53248 floats = 212992 B

// ---------------- device scratch ----------------
__device__ int g_fps[NCTR];
__device__ int g_prog[NB];      // per-cloud produced-center count
__device__ int g_tile_ctr;

// ---------------- helpers ----------------
__device__ __forceinline__ float dist2(float ax,float ay,float az,float bx,float by,float bz){
    float dx = ax - bx, dy = ay - by, dz = az - bz;
    return __fadd_rn(__fadd_rn(__fmul_rn(dx,dx), __fmul_rn(dy,dy)), __fmul_rn(dz,dz));
}
__device__ __forceinline__ float rna_tf32(float f){
    float o; asm("cvt.rna.tf32.f32 %0, %1;" : "=f"(o) : "f"(f)); return o;
}
__device__ __forceinline__ void st_rel(int* a, int v){
    asm volatile("st.release.gpu.global.s32 [%0], %1;" :: "l"(a), "r"(v) : "memory");
}
__device__ __forceinline__ int ld_acq(const int* a){
    int v; asm volatile("ld.acquire.gpu.global.s32 %0, [%1];" : "=r"(v) : "l"(a) : "memory");
    return v;
}

// ---- packed f32x2 (Blackwell base ISA; per-lane IEEE rn => bit-exact) ----
__device__ __forceinline__ uint64_t pack2(float lo, float hi){
    uint64_t r; asm("mov.b64 %0, {%1,%2};" : "=l"(r) : "f"(lo), "f"(hi)); return r;
}
__device__ __forceinline__ void unpack2(uint64_t v, float& lo, float& hi){
    asm("mov.b64 {%0,%1}, %2;" : "=f"(lo), "=f"(hi) : "l"(v));
}
#define SUB2(o,a,b) asm("sub.rn.f32x2 %0, %1, %2;" : "=l"(o) : "l"(a), "l"(b))
#define MUL2(o,a,b) asm("mul.rn.f32x2 %0, %1, %2;" : "=l"(o) : "l"(a), "l"(b))
#define ADD2(o,a,b) asm("add.rn.f32x2 %0, %1, %2;" : "=l"(o) : "l"(a), "l"(b))

#define MMA_TF32(d, a, b) \
    asm volatile("mma.sync.aligned.m16n8k8.row.col.f32.tf32.tf32.f32 " \
        "{%0,%1,%2,%3}, {%4,%5,%6,%7}, {%8,%9}, {%0,%1,%2,%3};" \
        : "+f"((d)[0]), "+f"((d)[1]), "+f"((d)[2]), "+f"((d)[3]) \
        : "r"((a)[0]), "r"((a)[1]), "r"((a)[2]), "r"((a)[3]), \
          "r"((b)[0]), "r"((b)[1]))

// ---------------------------------------------------------------------------
__global__ void init_kernel(){
    if (threadIdx.x == 0) g_tile_ctr = 0;
    if (threadIdx.x < NB) g_prog[threadIdx.x] = 0;
}

// ---------------------------------------------------------------------------
// Per-warp GEMM: 16 rows x 32 cols via 1x4 grid of m16n8k8 tf32 mma.sync.
// ---------------------------------------------------------------------------
template<int KSTEPS, int SA, int SB>
__device__ __forceinline__ void gemm_tile16(const float* __restrict__ As,
                                            const float* __restrict__ Bs,
                                            int warpR, int warpC, int g, int tg,
                                            float acc[4][4]){
    const uint32_t* Au = (const uint32_t*)As;
    const uint32_t* Bu = (const uint32_t*)Bs;
#pragma unroll 1
    for (int ks = 0; ks < KSTEPS; ++ks){
        int k0 = ks*8 + tg;
        uint32_t a[4], bf[4][2];
        const uint32_t* ar = Au + (warpR + g)*SA + k0;
        a[0] = ar[0];
        a[1] = ar[8*SA];
        a[2] = ar[4];
        a[3] = ar[8*SA + 4];
#pragma unroll
        for (int nt = 0; nt < 4; ++nt){
            const uint32_t* br = Bu + (warpC + nt*8 + g)*SB + k0;
            bf[nt][0] = br[0];
            bf[nt][1] = br[4];
        }
#pragma unroll
        for (int nt = 0; nt < 4; ++nt)
            MMA_TF32(acc[nt], a, bf[nt]);
    }
}

// ---------------------------------------------------------------------------
// Fused kernel: 148 blocks x 1024 threads, all co-resident (1 block/SM).
// ---------------------------------------------------------------------------
__global__ void __launch_bounds__(1024,1) fused_kernel(
        const float* __restrict__ x,  const float* __restrict__ pos,
        const float* __restrict__ W1, const float* __restrict__ b1,
        const float* __restrict__ W2, const float* __restrict__ b2,
        float* __restrict__ out, int out_size){
    extern __shared__ float sm[];
    float* W1s = sm + W1T_OFF;
    float* W2s = sm + W2T_OFF;
    float* A1s = sm + A1_OFF;
    float* A2s = sm + A2_OFF;

    __shared__ unsigned sv[2][32], si[2][32];    // FPS cross-warp stage
    __shared__ float sBox[32][8];                // per-warp AABB (lo3, hi3)
    __shared__ int cCnt[64];                     // cell histogram / offsets
    __shared__ int s_tile;
    __shared__ int s_cnt[2], s_M[2], s_nb[2][KNBR];
    __shared__ unsigned aggU[256];               // column-max agg (float bits, >=0)
    __shared__ float bbs[256];                   // b1 | b2

    int tid = threadIdx.x, w = tid >> 5, lane = tid & 31;
    const unsigned FULL = 0xffffffffu;

    // ======================= producer: FPS (blocks 0-7) =======================
    if (blockIdx.x < NB){
        int b = blockIdx.x;
        const float* p = pos + (size_t)b * NPER * 3;
        int*   sIdxArr = (int*)(sm + A1_OFF);    // [4096] persistent through FPS
        float* sXc = sm + A2_OFF;                // transient sort staging
        float* sYc = sXc + 4096;
        float* sZc = sYc + 4096;

        if (tid < 64) cCnt[tid] = 0;
        __syncthreads();

        // pass 1: load + cell histogram (4x4x4 grid)
        float lx[4], ly[4], lz[4]; int lc[4];
#pragma unroll
        for (int j = 0; j < 4; ++j){
            int i = tid + j*1024;
            lx[j] = p[i*3+0]; ly[j] = p[i*3+1]; lz[j] = p[i*3+2];
            int cxi = min(3, (int)(lx[j]*4.f));
            int cyi = min(3, (int)(ly[j]*4.f));
            int czi = min(3, (int)(lz[j]*4.f));
            lc[j] = cxi + 4*cyi + 16*czi;
            atomicAdd(&cCnt[lc[j]], 1);
        }
        __syncthreads();
        if (tid == 0){
            int acc = 0;
            for (int c2 = 0; c2 < 64; ++c2){ int t2 = cCnt[c2]; cCnt[c2] = acc; acc += t2; }
        }
        __syncthreads();
        // pass 2: scatter into cell-sorted order
#pragma unroll
        for (int j = 0; j < 4; ++j){
            int slot = atomicAdd(&cCnt[lc[j]], 1);
            sXc[slot] = lx[j]; sYc[slot] = ly[j]; sZc[slot] = lz[j];
            sIdxArr[slot] = tid + j*1024;
        }
        __syncthreads();

        // repack: warp w owns slots [w*128, w*128+128); lane's j-th at +lane+32j
        uint64_t PX[2], PY[2], PZ[2];
        float md[4];
        float mnx = 1e30f, mny = 1e30f, mnz = 1e30f;
        float mxx = -1e30f, mxy = -1e30f, mxz = -1e30f;
#pragma unroll
        for (int q = 0; q < 2; ++q){
            int s0 = w*128 + lane + 64*q, s1 = s0 + 32;
            float x0 = sXc[s0], x1 = sXc[s1];
            float y0 = sYc[s0], y1 = sYc[s1];
            float z0 = sZc[s0], z1 = sZc[s1];
            PX[q] = pack2(x0, x1); PY[q] = pack2(y0, y1); PZ[q] = pack2(z0, z1);
            md[2*q] = 1e10f; md[2*q+1] = 1e10f;
            mnx = fminf(mnx, fminf(x0, x1)); mxx = fmaxf(mxx, fmaxf(x0, x1));
            mny = fminf(mny, fminf(y0, y1)); mxy = fmaxf(mxy, fmaxf(y0, y1));
            mnz = fminf(mnz, fminf(z0, z1)); mxz = fmaxf(mxz, fmaxf(z0, z1));
        }
        // warp AABB via REDUX (coords in [0,1) -> uint order == float order)
        mnx = __uint_as_float(__reduce_min_sync(FULL, __float_as_uint(mnx)));
        mny = __uint_as_float(__reduce_min_sync(FULL, __float_as_uint(mny)));
        mnz = __uint_as_float(__reduce_min_sync(FULL, __float_as_uint(mnz)));
        mxx = __uint_as_float(__reduce_max_sync(FULL, __float_as_uint(mxx)));
        mxy = __uint_as_float(__reduce_max_sync(FULL, __float_as_uint(mxy)));
        mxz = __uint_as_float(__reduce_max_sync(FULL, __float_as_uint(mxz)));
        if (lane == 0){
            sBox[w][0] = mnx; sBox[w][1] = mny; sBox[w][2] = mnz;
            sBox[w][3] = mxx; sBox[w][4] = mxy; sBox[w][5] = mxz;
        }

        unsigned wv_c = __float_as_uint(1e10f);   // cached warp max (bits)
        unsigned wi_c = 0;                        // cached warp argmin index
        float cx = p[0], cy = p[1], cz = p[2];
        if (tid == 0) g_fps[b*NS] = 0;
        __syncthreads();

        for (int s = 1; s < NS; ++s){
            // warp-uniform exact skip test: dmin2(center, box) >= max md -> no-op
            float ddx = fmaxf(fmaxf(sBox[w][0] - cx, cx - sBox[w][3]), 0.f);
            float ddy = fmaxf(fmaxf(sBox[w][1] - cy, cy - sBox[w][4]), 0.f);
            float ddz = fmaxf(fmaxf(sBox[w][2] - cz, cz - sBox[w][5]), 0.f);
            float dmin2 = ddx*ddx + ddy*ddy + ddz*ddz;
            unsigned wv, wi;
            if (dmin2 < __uint_as_float(wv_c)){
                uint64_t CX2 = pack2(cx, cx), CY2 = pack2(cy, cy), CZ2 = pack2(cz, cz);
#pragma unroll
                for (int q = 0; q < 2; ++q){
                    uint64_t dx, dy, dz, xx, yy, zz, ss;
                    SUB2(dx, PX[q], CX2);
                    SUB2(dy, PY[q], CY2);
                    SUB2(dz, PZ[q], CZ2);
                    MUL2(xx, dx, dx);
                    MUL2(yy, dy, dy);
                    MUL2(zz, dz, dz);
                    ADD2(ss, xx, yy);
                    ADD2(ss, ss, zz);
                    float d0, d1; unpack2(ss, d0, d1);
                    md[2*q]   = fminf(md[2*q],   d0);
                    md[2*q+1] = fminf(md[2*q+1], d1);
                }
                float tv = fmaxf(fmaxf(md[0], md[1]), fmaxf(md[2], md[3]));
                wv = __reduce_max_sync(FULL, __float_as_uint(tv));
                unsigned mi = 0xFFFFFFFFu;
                if (__float_as_uint(tv) == wv){      // rare: winner threads fetch indices
#pragma unroll
                    for (int j = 0; j < 4; ++j){
                        if (__float_as_uint(md[j]) == wv){
                            int slot = w*128 + lane + 32*j;
                            mi = min(mi, (unsigned)sIdxArr[slot]);
                        }
                    }
                }
                wi = __reduce_min_sync(FULL, mi);
                wv_c = wv; wi_c = wi;
            } else {
                wv = wv_c; wi = wi_c;
            }

            int par = s & 1;
            if (lane == 0){ sv[par][w] = wv; si[par][w] = wi; }
            __syncthreads();

            unsigned lv = sv[par][lane];
            unsigned gv = __reduce_max_sync(FULL, lv);
            unsigned cand = (lv == gv) ? si[par][lane] : 0xFFFFFFFFu;
            unsigned gidx = __reduce_min_sync(FULL, cand);

            if (tid == 0){
                g_fps[b*NS + s] = (int)gidx;
                if ((s & 3) == 3) st_rel(&g_prog[b], s + 1);   // publish every 4
            }
            cx = p[gidx*3+0]; cy = p[gidx*3+1]; cz = p[gidx*3+2];
        }
        __syncthreads();
    }

    // ======================= consumer: all blocks =======================
    // stage weights (transpose + tf32-round) + biases
    for (int i = tid; i < 67*HDIM; i += 1024){
        int k = i >> 7, n = i & 127;
        W1s[n*S1 + k] = rna_tf32(W1[i]);
    }
    for (int i = tid; i < 128*5; i += 1024){          // zero pad k=67..71
        int n = i / 5, k = 67 + i % 5;
        W1s[n*S1 + k] = 0.f;
    }
    for (int i = tid; i < HDIM*HDIM; i += 1024){
        int k = i >> 7, n = i & 127;
        W2s[n*S2 + k] = rna_tf32(W2[i]);
    }
    if (tid < 128){ bbs[tid] = b1[tid]; bbs[128 + tid] = b2[tid]; }
    if (tid < 256) aggU[tid] = 0u;

    int g = lane >> 2, tg = lane & 3;
    int warpR = (w >> 2) * 16;     // 8 row-groups of 16 rows
    int warpC = (w & 3) * 32;      // 4 column blocks
    int center = warpR >> 6;       // 0 or 1
    __syncthreads();

    for (;;){
        if (tid == 0) s_tile = atomicAdd(&g_tile_ctr, 1);
        __syncthreads();
        int ticket = s_tile;
        if (ticket >= NTILES) break;
        int cloud = ticket & 7, pair = ticket >> 3;
        int c0 = cloud*NS + pair*2;

        // wait until both centers of this tile exist
        if (tid == 0){
            int need = pair*2 + 2, bo = 32;
            while (ld_acq(&g_prog[cloud]) < need){
                __nanosleep(bo);
                if (bo < 1024) bo <<= 1;
            }
        }
        __syncthreads();

        const float* p = pos + (size_t)cloud * NPER * 3;
        size_t base = (size_t)cloud * NPER;

        // ---- inlined select: 2 groups of 512 threads, one center each ----
        int grp = tid >> 9, lt = tid & 511;
        int ci = c0 + grp;
        int cidx = g_fps[ci];
        float cx = p[cidx*3+0], cy = p[cidx*3+1], cz = p[cidx*3+2];
        float* cdg = A2s + grp*CAP;
        int*   cig = ((int*)A2s) + 2*CAP + grp*CAP;
        if (lt == 0) s_cnt[grp] = 0;
        __syncthreads();

        for (int i = lt; i < NPER; i += 512){
            float d = dist2(p[i*3+0], p[i*3+1], p[i*3+2], cx, cy, cz);
            if (d <= R2){
                int q = atomicAdd(&s_cnt[grp], 1);
                if (q < CAP){ cdg[q] = d; cig[q] = i; }
            }
        }
        __syncthreads();
        int m = min(s_cnt[grp], CAP);
        if (m <= KNBR){
            for (int j = lt; j < m; j += 512) s_nb[grp][j] = cig[j];
            if (lt == 0) s_M[grp] = m;
        } else {
            for (int j = lt; j < m; j += 512){
                float dj = cdg[j]; int ij = cig[j];
                int r = 0;
                for (int u = 0; u < m; ++u){
                    float du = cdg[u];
                    r += (du < dj) || (du == dj && cig[u] < ij);
                }
                if (r < KNBR) s_nb[grp][r] = ij;
            }
            if (lt == 0) s_M[grp] = KNBR;
        }
        if (lt == 0 && out_size >= NCTR*HDIM + NCTR*3 + NCTR){
            float* po = out + NCTR*HDIM;
            po[ci*3+0] = cx; po[ci*3+1] = cy; po[ci*3+2] = cz;
            out[NCTR*HDIM + NCTR*3 + ci] = (float)cloud;
        }
        __syncthreads();
        int M0 = s_M[0], M1 = s_M[1];

        // ---- gather A1 [128 x 72] (tf32-rounded, zero-padded); 8 thr/row ----
        {
            int r = tid >> 3, q = tid & 7;
            int rg = r >> 6; int sl = r & 63;
            int M = rg ? M1 : M0;
            bool v = sl < M;
            float* arow = A1s + r*S1;
            const float4* xr = nullptr;
            int gl = 0;
            if (v){
                gl = s_nb[rg][sl];
                xr = (const float4*)(x + (base + gl)*CIN);
            }
            float4 t = v ? xr[q] : make_float4(0,0,0,0);
            t.x = rna_tf32(t.x); t.y = rna_tf32(t.y);
            t.z = rna_tf32(t.z); t.w = rna_tf32(t.w);
            *(float4*)(arow + 4*q) = t;
            t = v ? xr[q+8] : make_float4(0,0,0,0);
            t.x = rna_tf32(t.x); t.y = rna_tf32(t.y);
            t.z = rna_tf32(t.z); t.w = rna_tf32(t.w);
            *(float4*)(arow + 4*q + 32) = t;
            if (q == 0){
                float4 d4 = make_float4(0,0,0,0);
                if (v){
                    const float* pr = p + gl*3;
                    const float* pc = p + g_fps[c0 + rg]*3;
                    d4.x = rna_tf32(pr[0] - pc[0]);
                    d4.y = rna_tf32(pr[1] - pc[1]);
                    d4.z = rna_tf32(pr[2] - pc[2]);
                }
                *(float4*)(arow + 64) = d4;
            } else if (q == 1){
                *(float4*)(arow + 68) = make_float4(0,0,0,0);
            }
        }
        __syncthreads();

        // ---- GEMM1: [128x72] @ W1T -> relu+round -> A2 ----
        float acc[4][4];
#pragma unroll
        for (int nt = 0; nt < 4; ++nt)
#pragma unroll
            for (int i = 0; i < 4; ++i) acc[nt][i] = 0.f;
        gemm_tile16<9, S1, S1>(A1s, W1s, warpR, warpC, g, tg, acc);

        {
            int r0 = warpR + g;
#pragma unroll
            for (int nt = 0; nt < 4; ++nt){
                int cc = warpC + nt*8 + 2*tg;
                float ba = bbs[cc], bb = bbs[cc+1];
                float* d = acc[nt];
                float2 h0, h1;
                h0.x = rna_tf32(fmaxf(d[0] + ba, 0.f));
                h0.y = rna_tf32(fmaxf(d[1] + bb, 0.f));
                h1.x = rna_tf32(fmaxf(d[2] + ba, 0.f));
                h1.y = rna_tf32(fmaxf(d[3] + bb, 0.f));
                *(float2*)&A2s[r0*S2 + cc]     = h0;
                *(float2*)&A2s[(r0+8)*S2 + cc] = h1;
            }
        }
        __syncthreads();

        // ---- GEMM2: [128x128] @ W2T, fused relu + masked max ----
#pragma unroll
        for (int nt = 0; nt < 4; ++nt)
#pragma unroll
            for (int i = 0; i < 4; ++i) acc[nt][i] = 0.f;
        gemm_tile16<16, S2, S2>(A2s, W2s, warpR, warpC, g, tg, acc);

        {
            int M = center ? M1 : M0;
            int rIn = (warpR & 63) + g;
            bool v0 = rIn < M, v1 = (rIn + 8) < M;
            float cm[8];
#pragma unroll
            for (int i = 0; i < 8; ++i) cm[i] = 0.f;   // valid contributions are >= 0
#pragma unroll
            for (int nt = 0; nt < 4; ++nt){
                int cc = warpC + nt*8 + 2*tg;
                float ba = bbs[128+cc], bb = bbs[128+cc+1];
                float* d = acc[nt];
                if (v0){
                    cm[nt*2]   = fmaxf(cm[nt*2],   fmaxf(d[0] + ba, 0.f));
                    cm[nt*2+1] = fmaxf(cm[nt*2+1], fmaxf(d[1] + bb, 0.f));
                }
                if (v1){
                    cm[nt*2]   = fmaxf(cm[nt*2],   fmaxf(d[2] + ba, 0.f));
                    cm[nt*2+1] = fmaxf(cm[nt*2+1], fmaxf(d[3] + bb, 0.f));
                }
            }
#pragma unroll
            for (int o = 16; o >= 4; o >>= 1)
#pragma unroll
                for (int i = 0; i < 8; ++i)
                    cm[i] = fmaxf(cm[i], __shfl_down_sync(FULL, cm[i], o));
            if (lane < 4){       // g==0 lanes hold warp-level col maxima (tg=lane)
#pragma unroll
                for (int nt = 0; nt < 4; ++nt){
                    int cc = warpC + nt*8 + 2*lane;
                    atomicMax(&aggU[center*128 + cc],     __float_as_uint(cm[nt*2]));
                    atomicMax(&aggU[center*128 + cc + 1], __float_as_uint(cm[nt*2+1]));
                }
            }
        }
        __syncthreads();

        if (tid < 256){
            int cen = tid >> 7, col = tid & 127;
            out[(size_t)(c0 + cen)*HDIM + col] = __uint_as_float(aggU[tid]);
            aggU[tid] = 0u;      // reset for next ticket (same thread -> no race)
        }
    }
}

// ---------------------------------------------------------------------------
extern "C" void kernel_launch(void* const* d_in, const int* in_sizes, int n_in,
                              void* d_out, int out_size){
    const float *x = 0, *pos = 0, *W1 = 0, *b1 = 0, *W2 = 0, *b2 = 0;
    for (int i = 0; i < n_in; ++i){
        int s = in_sizes[i];
        const float* p = (const float*)d_in[i];
        if      (s == NB*NPER*CIN)  x   = p;
        else if (s == NB*NPER*3)    pos = p;
        else if (s == 67*HDIM)      W1  = p;
        else if (s == HDIM*HDIM)    W2  = p;
        else if (s == HDIM){ if (!b1) b1 = p; else b2 = p; }
    }
    float* out = (float*)d_out;

    size_t smem = SMEM_FLOATS * sizeof(float);
    cudaFuncSetAttribute(fused_kernel, cudaFuncAttributeMaxDynamicSharedMemorySize, (int)smem);

    init_kernel<<<1, 32>>>();
    fused_kernel<<<148, 1024, smem>>>(x, pos, W1, b1, W2, b2, out, out_size);
}